// round 13
// baseline (speedup 1.0000x reference)
#include <cuda_runtime.h>
#include <cstddef>

// Problem constants (fixed by the dataset)
#define NB 2
#define NP 4096
#define NA 96
#define NF 32
#define NE 20

#define THREADS 384      // 12 warps -> 3 per SMSP (balanced; 96-thr blocks left SMSP3 idle)
#define PPB 8            // p's per block: 384 threads * 2 items / 96 edges

#define L2E 1.4426950408889634f   // log2(e)
#define LN2 0.6931471805599453f   // ln(2)

// Scratch for precomputed linear terms (pre-scaled by log2e)
__device__ float g_tgt[NB * NP * NF];   // (srecv @ Wt + b1n) * log2e
__device__ float g_src[NB * NA * NF];   // (scalar @ Ws) * log2e

// Transformed weights for smem staging (written by precompute_kernel)
__device__ __align__(16) float g_W2n_s[NF * NF];  // ln2 * W2n
__device__ __align__(16) float g_b2n_s[NF];       // b2n - ln2*colsum(W2n)

// Single staging buffer for ALL const-bank data -> one D2D memcpy.
#define OFF_W1E 0
#define OFF_W2E (NE * NF)
#define OFF_B1E (NE * NF + NF * NF)
#define OFF_B2E (NE * NF + NF * NF + NF)
#define CG_SIZE (NE * NF + NF * NF + 2 * NF)
__device__ __align__(16) float g_cstage[CG_SIZE];
__constant__ __align__(16) float cG[CG_SIZE];

// minimal softplus core: y already scaled by log2e; returns log2(1 + 2^y).
__device__ __forceinline__ float ssp2(float y) {
    float e, t;
    asm("ex2.approx.f32 %0, %1;" : "=f"(e) : "f"(y));
    asm("lg2.approx.f32 %0, %1;" : "=f"(t) : "f"(1.0f + e));
    return t;
}

// ---- packed f32x2 helpers (Blackwell FFMA2) --------------------------------
__device__ __forceinline__ void fma2(unsigned long long& acc,
                                     unsigned long long s2,
                                     unsigned long long w2) {
    asm("fma.rn.f32x2 %0, %1, %2, %0;" : "+l"(acc) : "l"(s2), "l"(w2));
}
__device__ __forceinline__ unsigned long long pack2(float s) {
    unsigned long long r;
    asm("mov.b64 %0, {%1, %1};" : "=l"(r) : "f"(s));
    return r;
}
__device__ __forceinline__ float2 unpk2(unsigned long long v) {
    float2 r;
    asm("mov.b64 {%0, %1}, %2;" : "=f"(r.x), "=f"(r.y) : "l"(v));
    return r;
}

// ---------------------------------------------------------------------------
// Precompute kernel (prep merged in): one warp per output row, lane = f,
// plus weight transforms by global-thread-id ranges.
// ---------------------------------------------------------------------------
__global__ void precompute_kernel(const float* __restrict__ scalar,
                                  const float* __restrict__ srecv,
                                  const float* __restrict__ W1n,
                                  const float* __restrict__ b1n,
                                  const float* __restrict__ W1e,
                                  const float* __restrict__ b1e,
                                  const float* __restrict__ W2e,
                                  const float* __restrict__ b2e,
                                  const float* __restrict__ W2n,
                                  const float* __restrict__ b2n)
{
    int gid  = blockIdx.x * blockDim.x + threadIdx.x;
    int gw   = gid >> 5;
    int lane = threadIdx.x & 31;

    // ---- weight transforms (first few threads) ----
    if (gid < NE * NF) g_cstage[OFF_W1E + gid] = W1e[gid] * L2E;
    if (gid < NF * NF) {
        g_cstage[OFF_W2E + gid] = W2e[gid] * LN2;
        g_W2n_s[gid]            = W2n[gid] * LN2;
    }
    if (gid < NF) {
        g_cstage[OFF_B1E + gid] = b1e[gid] * L2E;
        float s2e = 0.0f, s2n = 0.0f;
        #pragma unroll
        for (int k = 0; k < NF; k++) {
            s2e += W2e[k * NF + gid];
            s2n += W2n[k * NF + gid];
        }
        g_cstage[OFF_B2E + gid] = b2e[gid] - LN2 * s2e;
        g_b2n_s[gid] = b2n[gid] - LN2 * s2n;
    }

    // ---- linear-term precompute ----
    if (gw < NB * NP) {
        float xv  = srecv[gw * NF + lane];
        float acc = b1n[lane];
        #pragma unroll
        for (int k = 0; k < NF; k++) {
            float xk = __shfl_sync(0xffffffffu, xv, k);
            acc = fmaf(xk, W1n[(NF + k) * NF + lane], acc);
        }
        g_tgt[gw * NF + lane] = acc * L2E;
    } else if (gw < NB * NP + NB * NA) {
        int r = gw - NB * NP;
        float xv  = scalar[r * NF + lane];
        float acc = 0.0f;
        #pragma unroll
        for (int k = 0; k < NF; k++) {
            float xk = __shfl_sync(0xffffffffu, xv, k);
            acc = fmaf(xk, W1n[k * NF + lane], acc);
        }
        g_src[r * NF + lane] = acc * L2E;
    }
}

// ---------------------------------------------------------------------------
// Main kernel: block = 8 (b,p)'s, 384 threads; thread = 2 edges (a, a+48)
// of p = t/48. Identical per-thread pipeline to the 107us R12 kernel; the
// only change is SMSP balance (12 warps -> 3 per sub-partition).
// Const port: W1e+W2e+biases. Smem: W2n. Base-2 softplus. FMA2 throughout.
// ---------------------------------------------------------------------------
extern __shared__ float sbuf[];   // [THREADS * 65] stash + reduction buffer

__global__ __launch_bounds__(THREADS, 1) void main_kernel(
    const float* __restrict__ expansion,   // (B,P,A,E)
    const float* __restrict__ mask,        // (B,P,A,1)
    const float* __restrict__ edge,        // (B,P,A,1)
    float* __restrict__ out)               // (B,P,1,F)
{
    __shared__ __align__(16) float sW2n[NF * NF];
    __shared__ __align__(16) float sb2n[NF];
    __shared__ __align__(16) float stgt[PPB][NF];

    const int t   = threadIdx.x;                // 0..383
    const int pl  = t / 48;                     // which p within the block
    const int ai  = t - pl * 48;                // 0..47
    const int bp  = PPB * blockIdx.x + pl;      // global b*NP+p
    const int b   = bp >> 12;                   // NP == 4096
    const int a0  = ai;                         // first edge
    const int a1  = ai + 48;                    // second edge

    // ---- cooperative staging ----
    for (int i = t; i < NF * NF; i += THREADS) sW2n[i] = g_W2n_s[i];
    if (t < NF) sb2n[t] = g_b2n_s[t];
    if (t < PPB * NF) {
        stgt[t >> 5][t & 31] =
            g_tgt[(size_t)(PPB * blockIdx.x + (t >> 5)) * NF + (t & 31)];
    }
    __syncthreads();

    // ---- per-item edge data ----
    const size_t base0 = (size_t)bp * NA + a0;
    const size_t base1 = (size_t)bp * NA + a1;

    float x0[NE], x1[NE];
    {
        const float4* r0 = reinterpret_cast<const float4*>(expansion + base0 * NE);
        const float4* r1 = reinterpret_cast<const float4*>(expansion + base1 * NE);
        #pragma unroll
        for (int i = 0; i < NE / 4; i++) {
            float4 v0 = r0[i], v1 = r1[i];
            x0[4*i+0] = v0.x; x0[4*i+1] = v0.y; x0[4*i+2] = v0.z; x0[4*i+3] = v0.w;
            x1[4*i+0] = v1.x; x1[4*i+1] = v1.y; x1[4*i+2] = v1.z; x1[4*i+3] = v1.w;
        }
    }
    float gm0, gm1;
    {
        float m0 = mask[base0], m1 = mask[base1];
        float d0 = edge[base0], d1 = edge[base1];
        float u0, u1;
        asm("ex2.approx.f32 %0, %1;" : "=f"(u0) : "f"((d0 - 3.5f) * (5.0f * L2E)));
        asm("ex2.approx.f32 %0, %1;" : "=f"(u1) : "f"((d1 - 3.5f) * (5.0f * L2E)));
        gm0 = __fdividef(m0, 1.0f + u0);
        gm1 = __fdividef(m1, 1.0f + u1);
    }

    // ===== gates layer 1: (x @ W1e' + b1e')  [weights: constant port] =====
    unsigned long long acc0[NF / 2], acc1[NF / 2];
    {
        const unsigned long long* bb =
            reinterpret_cast<const unsigned long long*>(&cG[OFF_B1E]);
        #pragma unroll
        for (int j = 0; j < NF / 2; j++) { acc0[j] = bb[j]; acc1[j] = bb[j]; }
    }
    #pragma unroll
    for (int e = 0; e < NE; e++) {
        unsigned long long s0 = pack2(x0[e]);
        unsigned long long s1 = pack2(x1[e]);
        const ulonglong2* w4 =
            reinterpret_cast<const ulonglong2*>(&cG[OFF_W1E + e * NF]);
        #pragma unroll
        for (int j = 0; j < NF / 4; j++) {
            ulonglong2 w = w4[j];
            fma2(acc0[2*j+0], s0, w.x); fma2(acc1[2*j+0], s1, w.x);
            fma2(acc0[2*j+1], s0, w.y); fma2(acc1[2*j+1], s1, w.y);
        }
    }
    float e1g0[NF], e1g1[NF];
    #pragma unroll
    for (int j = 0; j < NF / 2; j++) {
        float2 v0 = unpk2(acc0[j]), v1 = unpk2(acc1[j]);
        e1g0[2*j+0] = ssp2(v0.x); e1g0[2*j+1] = ssp2(v0.y);
        e1g1[2*j+0] = ssp2(v1.x); e1g1[2*j+1] = ssp2(v1.y);
    }

    // ===== gates layer 2: @ W2e' + b2e'  [weights: constant port] =====
    {
        const unsigned long long* bb =
            reinterpret_cast<const unsigned long long*>(&cG[OFF_B2E]);
        #pragma unroll
        for (int j = 0; j < NF / 2; j++) { acc0[j] = bb[j]; acc1[j] = bb[j]; }
    }
    #pragma unroll
    for (int k = 0; k < NF; k++) {
        unsigned long long s0 = pack2(e1g0[k]);
        unsigned long long s1 = pack2(e1g1[k]);
        const ulonglong2* w4 =
            reinterpret_cast<const ulonglong2*>(&cG[OFF_W2E + k * NF]);
        #pragma unroll
        for (int j = 0; j < NF / 4; j++) {
            ulonglong2 w = w4[j];
            fma2(acc0[2*j+0], s0, w.x); fma2(acc1[2*j+0], s1, w.x);
            fma2(acc0[2*j+1], s0, w.y); fma2(acc1[2*j+1], s1, w.y);
        }
    }
    // stash gm * gate to smem (frees 64 registers for the nodes GEMM)
    {
        float* st = &sbuf[t * 65];
        #pragma unroll
        for (int j = 0; j < NF / 2; j++) {
            float2 v0 = unpk2(acc0[j]), v1 = unpk2(acc1[j]);
            st[2*j+0]      = gm0 * v0.x;  st[2*j+1]      = gm0 * v0.y;
            st[NF + 2*j+0] = gm1 * v1.x;  st[NF + 2*j+1] = gm1 * v1.y;
        }
    }

    // ===== nodes path: ssp2(src'[a] + tgt'[p]) @ W2n' + b2n'  [smem] ========
    float n1g0[NF], n1g1[NF];
    {
        const float4* s0 = reinterpret_cast<const float4*>(g_src + ((size_t)b * NA + a0) * NF);
        const float4* s1 = reinterpret_cast<const float4*>(g_src + ((size_t)b * NA + a1) * NF);
        #pragma unroll
        for (int q = 0; q < NF / 4; q++) {
            float4 v0 = s0[q], v1 = s1[q];
            float t0 = stgt[pl][4*q+0], t1 = stgt[pl][4*q+1];
            float t2 = stgt[pl][4*q+2], t3 = stgt[pl][4*q+3];
            n1g0[4*q+0] = ssp2(v0.x + t0); n1g0[4*q+1] = ssp2(v0.y + t1);
            n1g0[4*q+2] = ssp2(v0.z + t2); n1g0[4*q+3] = ssp2(v0.w + t3);
            n1g1[4*q+0] = ssp2(v1.x + t0); n1g1[4*q+1] = ssp2(v1.y + t1);
            n1g1[4*q+2] = ssp2(v1.z + t2); n1g1[4*q+3] = ssp2(v1.w + t3);
        }
    }
    {
        const unsigned long long* bb = reinterpret_cast<const unsigned long long*>(sb2n);
        #pragma unroll
        for (int j = 0; j < NF / 2; j++) { acc0[j] = bb[j]; acc1[j] = bb[j]; }
    }
    #pragma unroll
    for (int k = 0; k < NF; k++) {
        unsigned long long s0 = pack2(n1g0[k]);
        unsigned long long s1 = pack2(n1g1[k]);
        const ulonglong2* w4 = reinterpret_cast<const ulonglong2*>(&sW2n[k * NF]);
        #pragma unroll
        for (int j = 0; j < NF / 4; j++) {
            ulonglong2 w = w4[j];
            fma2(acc0[2*j+0], s0, w.x); fma2(acc1[2*j+0], s1, w.x);
            fma2(acc0[2*j+1], s0, w.y); fma2(acc1[2*j+1], s1, w.y);
        }
    }

    // ---- combine both items in registers: r_f = st0_f*n0_f + st1_f*n1_f ----
    float r[NF];
    {
        const float* st = &sbuf[t * 65];
        #pragma unroll
        for (int j = 0; j < NF / 2; j++) {
            float2 v0 = unpk2(acc0[j]), v1 = unpk2(acc1[j]);
            r[2*j+0] = fmaf(st[2*j+0], v0.x, st[NF + 2*j+0] * v1.x);
            r[2*j+1] = fmaf(st[2*j+1], v0.y, st[NF + 2*j+1] * v1.y);
        }
    }

    __syncthreads();   // stash fully consumed; reuse sbuf for reduction

    #pragma unroll
    for (int f = 0; f < NF; f++) sbuf[t * 65 + f] = r[f];

    __syncthreads();

    // ---- reduce 48 thread-rows per p, write coalesced output ----
    // threads [0, PPB*32): pp = t>>5 selects p, f = t&31 selects feature
    if (t < PPB * NF) {
        int pp = t >> 5;
        int f  = t & 31;
        float s = 0.0f;
        #pragma unroll
        for (int row = 0; row < 48; row++) s += sbuf[(pp * 48 + row) * 65 + f];
        out[(size_t)(PPB * blockIdx.x + pp) * NF + f] = s;
    }
}

// ---------------------------------------------------------------------------
// Launch: 3 graph nodes (precompute+prep, one const memcpy, main)
// ---------------------------------------------------------------------------
extern "C" void kernel_launch(void* const* d_in, const int* in_sizes, int n_in,
                              void* d_out, int out_size)
{
    const float* scalar    = (const float*)d_in[0];
    const float* srecv     = (const float*)d_in[1];
    const float* expansion = (const float*)d_in[2];
    const float* mask      = (const float*)d_in[3];
    const float* edge      = (const float*)d_in[4];
    const float* W1e       = (const float*)d_in[5];
    const float* b1e       = (const float*)d_in[6];
    const float* W2e       = (const float*)d_in[7];
    const float* b2e       = (const float*)d_in[8];
    const float* W1n       = (const float*)d_in[9];
    const float* b1n       = (const float*)d_in[10];
    const float* W2n       = (const float*)d_in[11];
    const float* b2n       = (const float*)d_in[12];
    float* out = (float*)d_out;

    // Opt in to >48KB dynamic smem for the stash/reduction buffer.
    // (Attribute set, not an allocation; not stream-ordered -> capture-safe.)
    const int dyn_smem = THREADS * 65 * (int)sizeof(float);   // 99840 B
    cudaFuncSetAttribute(main_kernel,
                         cudaFuncAttributeMaxDynamicSharedMemorySize, dyn_smem);

    // 1) Precompute linear terms + all weight transforms in one launch
    int rows    = NB * NP + NB * NA;               // 8384
    int threads = 256;
    int blocks  = (rows * 32 + threads - 1) / threads;
    precompute_kernel<<<blocks, threads>>>(scalar, srecv, W1n, b1n,
                                           W1e, b1e, W2e, b2e, W2n, b2n);

    // 2) Single D2D copy of all const-bank data
    void* pstage = nullptr;
    cudaGetSymbolAddress(&pstage, g_cstage);
    cudaMemcpyToSymbolAsync(cG, pstage, CG_SIZE * sizeof(float), 0,
                            cudaMemcpyDeviceToDevice, 0);

    // 3) Main fused kernel: one block per 8 (b,p)'s, 12 balanced warps
    main_kernel<<<NB * NP / PPB, THREADS, dyn_smem>>>(expansion, mask, edge, out);
}

// round 14
// speedup vs baseline: 1.0430x; 1.0430x over previous
#include <cuda_runtime.h>
#include <cstddef>

// Problem constants (fixed by the dataset)
#define NB 2
#define NP 4096
#define NA 96
#define NF 32
#define NE 20

#define L2E 1.4426950408889634f   // log2(e)
#define LN2 0.6931471805599453f   // ln(2)

// Scratch for precomputed linear terms (pre-scaled by log2e)
__device__ float g_tgt[NB * NP * NF];   // (srecv @ Wt + b1n) * log2e
__device__ float g_src[NB * NA * NF];   // (scalar @ Ws) * log2e

// Transformed weights for smem staging (written by precompute_kernel)
__device__ __align__(16) float g_W2n_s[NF * NF];  // ln2 * W2n
__device__ __align__(16) float g_b2n_s[NF];       // b2n - ln2*colsum(W2n)

// Single staging buffer for ALL const-bank data -> one D2D memcpy.
// Layout: [0,640) W1e*log2e | [640,1664) W2e*ln2
//         [1664,1696) b1e*log2e | [1696,1728) b2e - ln2*colsum(W2e)
#define OFF_W1E 0
#define OFF_W2E (NE * NF)
#define OFF_B1E (NE * NF + NF * NF)
#define OFF_B2E (NE * NF + NF * NF + NF)
#define CG_SIZE (NE * NF + NF * NF + 2 * NF)
__device__ __align__(16) float g_cstage[CG_SIZE];
__constant__ __align__(16) float cG[CG_SIZE];

// minimal softplus core: y already scaled by log2e; returns log2(1 + 2^y).
// Downstream ln2 scale / -ln2 shift folded into W'/b'. 2 MUFU + 1 FADD.
__device__ __forceinline__ float ssp2(float y) {
    float e, t;
    asm("ex2.approx.f32 %0, %1;" : "=f"(e) : "f"(y));
    asm("lg2.approx.f32 %0, %1;" : "=f"(t) : "f"(1.0f + e));
    return t;
}

// ---- packed f32x2 helpers (Blackwell FFMA2) --------------------------------
__device__ __forceinline__ void fma2(unsigned long long& acc,
                                     unsigned long long s2,
                                     unsigned long long w2) {
    asm("fma.rn.f32x2 %0, %1, %2, %0;" : "+l"(acc) : "l"(s2), "l"(w2));
}
__device__ __forceinline__ unsigned long long pack2(float s) {
    unsigned long long r;
    asm("mov.b64 %0, {%1, %1};" : "=l"(r) : "f"(s));
    return r;
}
__device__ __forceinline__ float2 unpk2(unsigned long long v) {
    float2 r;
    asm("mov.b64 {%0, %1}, %2;" : "=f"(r.x), "=f"(r.y) : "l"(v));
    return r;
}

// ---------------------------------------------------------------------------
// Precompute kernel (prep merged in): one warp per output row, lane = f,
// plus weight transforms by global-thread-id ranges.
// ---------------------------------------------------------------------------
__global__ void precompute_kernel(const float* __restrict__ scalar,
                                  const float* __restrict__ srecv,
                                  const float* __restrict__ W1n,
                                  const float* __restrict__ b1n,
                                  const float* __restrict__ W1e,
                                  const float* __restrict__ b1e,
                                  const float* __restrict__ W2e,
                                  const float* __restrict__ b2e,
                                  const float* __restrict__ W2n,
                                  const float* __restrict__ b2n)
{
    int gid  = blockIdx.x * blockDim.x + threadIdx.x;
    int gw   = gid >> 5;
    int lane = threadIdx.x & 31;

    // ---- weight transforms (first few threads) ----
    if (gid < NE * NF) g_cstage[OFF_W1E + gid] = W1e[gid] * L2E;
    if (gid < NF * NF) {
        g_cstage[OFF_W2E + gid] = W2e[gid] * LN2;
        g_W2n_s[gid]            = W2n[gid] * LN2;
    }
    if (gid < NF) {
        g_cstage[OFF_B1E + gid] = b1e[gid] * L2E;
        float s2e = 0.0f, s2n = 0.0f;
        #pragma unroll
        for (int k = 0; k < NF; k++) {
            s2e += W2e[k * NF + gid];
            s2n += W2n[k * NF + gid];
        }
        g_cstage[OFF_B2E + gid] = b2e[gid] - LN2 * s2e;
        g_b2n_s[gid] = b2n[gid] - LN2 * s2n;
    }

    // ---- linear-term precompute ----
    if (gw < NB * NP) {
        float xv  = srecv[gw * NF + lane];
        float acc = b1n[lane];
        #pragma unroll
        for (int k = 0; k < NF; k++) {
            float xk = __shfl_sync(0xffffffffu, xv, k);
            acc = fmaf(xk, W1n[(NF + k) * NF + lane], acc);
        }
        g_tgt[gw * NF + lane] = acc * L2E;
    } else if (gw < NB * NP + NB * NA) {
        int r = gw - NB * NP;
        float xv  = scalar[r * NF + lane];
        float acc = 0.0f;
        #pragma unroll
        for (int k = 0; k < NF; k++) {
            float xk = __shfl_sync(0xffffffffu, xv, k);
            acc = fmaf(xk, W1n[k * NF + lane], acc);
        }
        g_src[r * NF + lane] = acc * L2E;
    }
}

// ---------------------------------------------------------------------------
// Main kernel: block = 2 (b,p)'s; thread = 2 edges (a, a+48) of one p.
// R12 layout (best): W1e + W2e + biases on const port, W2n on smem.
// NEW: just-in-time ssp2 (lookahead 4) inside gates-2 and nodes GEMMs so
// MUFU issue interleaves with FMA2 instead of bursting 64-deep.
// ---------------------------------------------------------------------------
__global__ __launch_bounds__(96, 4) void main_kernel(
    const float* __restrict__ expansion,   // (B,P,A,E)
    const float* __restrict__ mask,        // (B,P,A,1)
    const float* __restrict__ edge,        // (B,P,A,1)
    float* __restrict__ out)               // (B,P,1,F)
{
    __shared__ __align__(16) float sW2n[NF * NF];
    __shared__ __align__(16) float sb2n[NF];
    __shared__ __align__(16) float stgt[2][NF];
    // Reused: gate stash (64 f/thread, stride 65) then reduction buffer.
    __shared__ float sbuf[96 * 65];

    const int t   = threadIdx.x;          // 0..95
    const int pl  = t / 48;               // which p within the block
    const int ai  = t - pl * 48;          // 0..47
    const int bp  = 2 * blockIdx.x + pl;  // global b*NP+p
    const int b   = bp >> 12;             // NP == 4096
    const int a0  = ai;                   // first edge
    const int a1  = ai + 48;              // second edge

    // ---- cooperative staging ----
    for (int i = t; i < NF * NF; i += 96) sW2n[i] = g_W2n_s[i];
    if (t < NF) {
        sb2n[t] = g_b2n_s[t];
        stgt[0][t] = g_tgt[(size_t)(2 * blockIdx.x) * NF + t];
        stgt[1][t] = g_tgt[(size_t)(2 * blockIdx.x + 1) * NF + t];
    }
    __syncthreads();

    // ---- per-item edge data ----
    const size_t base0 = (size_t)bp * NA + a0;
    const size_t base1 = (size_t)bp * NA + a1;

    float x0[NE], x1[NE];
    {
        const float4* r0 = reinterpret_cast<const float4*>(expansion + base0 * NE);
        const float4* r1 = reinterpret_cast<const float4*>(expansion + base1 * NE);
        #pragma unroll
        for (int i = 0; i < NE / 4; i++) {
            float4 v0 = r0[i], v1 = r1[i];
            x0[4*i+0] = v0.x; x0[4*i+1] = v0.y; x0[4*i+2] = v0.z; x0[4*i+3] = v0.w;
            x1[4*i+0] = v1.x; x1[4*i+1] = v1.y; x1[4*i+2] = v1.z; x1[4*i+3] = v1.w;
        }
    }
    float gm0, gm1;
    {
        float m0 = mask[base0], m1 = mask[base1];
        float d0 = edge[base0], d1 = edge[base1];
        // sigmoid cutoff in base-2: 1/(1+2^{5*log2e*(d-3.5)})
        float u0, u1;
        asm("ex2.approx.f32 %0, %1;" : "=f"(u0) : "f"((d0 - 3.5f) * (5.0f * L2E)));
        asm("ex2.approx.f32 %0, %1;" : "=f"(u1) : "f"((d1 - 3.5f) * (5.0f * L2E)));
        gm0 = __fdividef(m0, 1.0f + u0);
        gm1 = __fdividef(m1, 1.0f + u1);
    }

    // ===== gates layer 1: (x @ W1e' + b1e')  [weights: constant port] =====
    unsigned long long acc0[NF / 2], acc1[NF / 2];
    {
        const unsigned long long* bb =
            reinterpret_cast<const unsigned long long*>(&cG[OFF_B1E]);
        #pragma unroll
        for (int j = 0; j < NF / 2; j++) { acc0[j] = bb[j]; acc1[j] = bb[j]; }
    }
    #pragma unroll
    for (int e = 0; e < NE; e++) {
        unsigned long long s0 = pack2(x0[e]);
        unsigned long long s1 = pack2(x1[e]);
        const ulonglong2* w4 =
            reinterpret_cast<const ulonglong2*>(&cG[OFF_W1E + e * NF]);
        #pragma unroll
        for (int j = 0; j < NF / 4; j++) {
            ulonglong2 w = w4[j];
            fma2(acc0[2*j+0], s0, w.x); fma2(acc1[2*j+0], s1, w.x);
            fma2(acc0[2*j+1], s0, w.y); fma2(acc1[2*j+1], s1, w.y);
        }
    }
    // raw pre-activations into registers (no MUFU burst here)
    float e1g0[NF], e1g1[NF];
    #pragma unroll
    for (int j = 0; j < NF / 2; j++) {
        float2 v0 = unpk2(acc0[j]), v1 = unpk2(acc1[j]);
        e1g0[2*j+0] = v0.x; e1g0[2*j+1] = v0.y;
        e1g1[2*j+0] = v1.x; e1g1[2*j+1] = v1.y;
    }
    // prologue: ssp2 for the first 4 k's
    #pragma unroll
    for (int k = 0; k < 4; k++) { e1g0[k] = ssp2(e1g0[k]); e1g1[k] = ssp2(e1g1[k]); }

    // ===== gates layer 2: @ W2e' + b2e'  [weights: const port; ssp2 JIT] ===
    {
        const unsigned long long* bb =
            reinterpret_cast<const unsigned long long*>(&cG[OFF_B2E]);
        #pragma unroll
        for (int j = 0; j < NF / 2; j++) { acc0[j] = bb[j]; acc1[j] = bb[j]; }
    }
    #pragma unroll
    for (int k = 0; k < NF; k++) {
        if (k + 4 < NF) {   // JIT ssp2, lookahead 4 (static guard, unrolled)
            e1g0[k + 4] = ssp2(e1g0[k + 4]);
            e1g1[k + 4] = ssp2(e1g1[k + 4]);
        }
        unsigned long long s0 = pack2(e1g0[k]);
        unsigned long long s1 = pack2(e1g1[k]);
        const ulonglong2* w4 =
            reinterpret_cast<const ulonglong2*>(&cG[OFF_W2E + k * NF]);
        #pragma unroll
        for (int j = 0; j < NF / 4; j++) {
            ulonglong2 w = w4[j];
            fma2(acc0[2*j+0], s0, w.x); fma2(acc1[2*j+0], s1, w.x);
            fma2(acc0[2*j+1], s0, w.y); fma2(acc1[2*j+1], s1, w.y);
        }
    }
    // stash gm * gate to smem (frees 64 registers for the nodes GEMM)
    {
        float* st = &sbuf[t * 65];
        #pragma unroll
        for (int j = 0; j < NF / 2; j++) {
            float2 v0 = unpk2(acc0[j]), v1 = unpk2(acc1[j]);
            st[2*j+0]      = gm0 * v0.x;  st[2*j+1]      = gm0 * v0.y;
            st[NF + 2*j+0] = gm1 * v1.x;  st[NF + 2*j+1] = gm1 * v1.y;
        }
    }

    // ===== nodes path: ssp2(src'[a] + tgt'[p]) @ W2n' + b2n'  [ssp2 JIT] ====
    float n1g0[NF], n1g1[NF];
    {
        // raw pre-activations: FADD only
        const float4* s0 = reinterpret_cast<const float4*>(g_src + ((size_t)b * NA + a0) * NF);
        const float4* s1 = reinterpret_cast<const float4*>(g_src + ((size_t)b * NA + a1) * NF);
        #pragma unroll
        for (int q = 0; q < NF / 4; q++) {
            float4 v0 = s0[q], v1 = s1[q];
            float t0 = stgt[pl][4*q+0], t1 = stgt[pl][4*q+1];
            float t2 = stgt[pl][4*q+2], t3 = stgt[pl][4*q+3];
            n1g0[4*q+0] = v0.x + t0; n1g0[4*q+1] = v0.y + t1;
            n1g0[4*q+2] = v0.z + t2; n1g0[4*q+3] = v0.w + t3;
            n1g1[4*q+0] = v1.x + t0; n1g1[4*q+1] = v1.y + t1;
            n1g1[4*q+2] = v1.z + t2; n1g1[4*q+3] = v1.w + t3;
        }
    }
    #pragma unroll
    for (int k = 0; k < 4; k++) { n1g0[k] = ssp2(n1g0[k]); n1g1[k] = ssp2(n1g1[k]); }

    {
        const unsigned long long* bb = reinterpret_cast<const unsigned long long*>(sb2n);
        #pragma unroll
        for (int j = 0; j < NF / 2; j++) { acc0[j] = bb[j]; acc1[j] = bb[j]; }
    }
    #pragma unroll
    for (int k = 0; k < NF; k++) {
        if (k + 4 < NF) {   // JIT ssp2, lookahead 4
            n1g0[k + 4] = ssp2(n1g0[k + 4]);
            n1g1[k + 4] = ssp2(n1g1[k + 4]);
        }
        unsigned long long s0 = pack2(n1g0[k]);
        unsigned long long s1 = pack2(n1g1[k]);
        const ulonglong2* w4 = reinterpret_cast<const ulonglong2*>(&sW2n[k * NF]);
        #pragma unroll
        for (int j = 0; j < NF / 4; j++) {
            ulonglong2 w = w4[j];
            fma2(acc0[2*j+0], s0, w.x); fma2(acc1[2*j+0], s1, w.x);
            fma2(acc0[2*j+1], s0, w.y); fma2(acc1[2*j+1], s1, w.y);
        }
    }

    // ---- combine both items in registers: r_f = st0_f*n0_f + st1_f*n1_f ----
    float r[NF];
    {
        const float* st = &sbuf[t * 65];
        #pragma unroll
        for (int j = 0; j < NF / 2; j++) {
            float2 v0 = unpk2(acc0[j]), v1 = unpk2(acc1[j]);
            r[2*j+0] = fmaf(st[2*j+0], v0.x, st[NF + 2*j+0] * v1.x);
            r[2*j+1] = fmaf(st[2*j+1], v0.y, st[NF + 2*j+1] * v1.y);
        }
    }

    __syncthreads();   // stash fully consumed; reuse sbuf for reduction

    #pragma unroll
    for (int f = 0; f < NF; f++) sbuf[t * 65 + f] = r[f];

    __syncthreads();

    // ---- reduce 48 thread-rows per p, write coalesced output ----
    if (t < NF) {
        float s = 0.0f;
        #pragma unroll
        for (int row = 0; row < 48; row++) s += sbuf[row * 65 + t];
        out[(size_t)(2 * blockIdx.x) * NF + t] = s;
    } else if (t >= 48 && t < 48 + NF) {
        int f = t - 48;
        float s = 0.0f;
        #pragma unroll
        for (int row = 48; row < 96; row++) s += sbuf[row * 65 + f];
        out[(size_t)(2 * blockIdx.x + 1) * NF + f] = s;
    }
}

// ---------------------------------------------------------------------------
// Launch: 3 graph nodes total (precompute+prep, one const memcpy, main)
// ---------------------------------------------------------------------------
extern "C" void kernel_launch(void* const* d_in, const int* in_sizes, int n_in,
                              void* d_out, int out_size)
{
    const float* scalar    = (const float*)d_in[0];
    const float* srecv     = (const float*)d_in[1];
    const float* expansion = (const float*)d_in[2];
    const float* mask      = (const float*)d_in[3];
    const float* edge      = (const float*)d_in[4];
    const float* W1e       = (const float*)d_in[5];
    const float* b1e       = (const float*)d_in[6];
    const float* W2e       = (const float*)d_in[7];
    const float* b2e       = (const float*)d_in[8];
    const float* W1n       = (const float*)d_in[9];
    const float* b1n       = (const float*)d_in[10];
    const float* W2n       = (const float*)d_in[11];
    const float* b2n       = (const float*)d_in[12];
    float* out = (float*)d_out;

    // 1) Precompute linear terms + all weight transforms in one launch
    int rows    = NB * NP + NB * NA;               // 8384
    int threads = 256;
    int blocks  = (rows * 32 + threads - 1) / threads;
    precompute_kernel<<<blocks, threads>>>(scalar, srecv, W1n, b1n,
                                           W1e, b1e, W2e, b2e, W2n, b2n);

    // 2) Single D2D copy of all const-bank data
    void* pstage = nullptr;
    cudaGetSymbolAddress(&pstage, g_cstage);
    cudaMemcpyToSymbolAsync(cG, pstage, CG_SIZE * sizeof(float), 0,
                            cudaMemcpyDeviceToDevice, 0);

    // 3) Main fused kernel: one block per 2 (b,p)'s
    main_kernel<<<NB * NP / 2, 96>>>(expansion, mask, edge, out);
}